// round 17
// baseline (speedup 1.0000x reference)
#include <cuda_runtime.h>
#include <cuda_bf16.h>
#include <cuda_fp16.h>
#include <math.h>
#include <stdint.h>

#define HIDDEN 2048
#define HEADS 16
#define HD 128
#define SEQL 2048
#define NBATCH 2
#define MROWS (NBATCH * SEQL) // 4096
#define KDIM 2048

// ---------------------------------------------------------------------------
// Scratch: __device__ globals (no cudaMalloc allowed)
// ---------------------------------------------------------------------------
__device__ float g_q[(size_t)MROWS * HIDDEN];
__device__ float g_k[(size_t)MROWS * HIDDEN];
__device__ float g_v[(size_t)MROWS * HIDDEN];
__device__ float g_o[(size_t)MROWS * HIDDEN];

// fp16 single-rounded operands (all projections)
__device__ __half g_x16[(size_t)MROWS * HIDDEN];
__device__ __half g_o16[(size_t)MROWS * HIDDEN];
__device__ __half g_wq16[(size_t)HIDDEN * HIDDEN];
__device__ __half g_wk16[(size_t)HIDDEN * HIDDEN];
__device__ __half g_wv16[(size_t)HIDDEN * HIDDEN];
__device__ __half g_wo16[(size_t)HIDDEN * HIDDEN];

// fp16 split Q (hi/lo), single-rounded K, transposed V for flash
__device__ __half g_qh16[(size_t)MROWS * HIDDEN];
__device__ __half g_ql16[(size_t)MROWS * HIDDEN];
__device__ __half g_kh16[(size_t)MROWS * HIDDEN];
__device__ __half g_vt16[(size_t)MROWS * HIDDEN];

// ---------------------------------------------------------------------------
__device__ __forceinline__ void mma16816h(float* c, const uint32_t* a, const uint32_t* b)
{
    asm volatile(
        "mma.sync.aligned.m16n8k16.row.col.f32.f16.f16.f32 "
        "{%0,%1,%2,%3}, {%4,%5,%6,%7}, {%8,%9}, {%0,%1,%2,%3};"
        : "+f"(c[0]), "+f"(c[1]), "+f"(c[2]), "+f"(c[3])
        : "r"(a[0]), "r"(a[1]), "r"(a[2]), "r"(a[3]), "r"(b[0]), "r"(b[1]));
}

#define LDSM4(r0, r1, r2, r3, addr) \
    asm volatile("ldmatrix.sync.aligned.m8n8.x4.shared.b16 {%0,%1,%2,%3}, [%4];" \
                 : "=r"(r0), "=r"(r1), "=r"(r2), "=r"(r3) : "r"(addr))

// ---------------------------------------------------------------------------
// Round fp32 -> fp16 (single tensor)
// ---------------------------------------------------------------------------
__global__ void round_h_kernel(const float4* __restrict__ a,
                               __half* __restrict__ hi, int n4)
{
    int i = blockIdx.x * blockDim.x + threadIdx.x;
    if (i >= n4) return;
    float4 v = a[i];
    ushort4 hv;
    hv.x = __half_as_ushort(__float2half_rn(v.x));
    hv.y = __half_as_ushort(__float2half_rn(v.y));
    hv.z = __half_as_ushort(__float2half_rn(v.z));
    hv.w = __half_as_ushort(__float2half_rn(v.w));
    *(ushort4*)(hi + (size_t)i * 4) = hv;
}

// Round fp32 -> fp16 for 4 tensors in one launch (grid.z selects)
__global__ void round_h4_kernel(const float4* __restrict__ a0, __half* __restrict__ d0,
                                const float4* __restrict__ a1, __half* __restrict__ d1,
                                const float4* __restrict__ a2, __half* __restrict__ d2,
                                const float4* __restrict__ a3, __half* __restrict__ d3,
                                int n4)
{
    int i = blockIdx.x * blockDim.x + threadIdx.x;
    if (i >= n4) return;
    const int z = blockIdx.z;
    const float4* a = (z == 0) ? a0 : (z == 1) ? a1 : (z == 2) ? a2 : a3;
    __half* d = (z == 0) ? d0 : (z == 1) ? d1 : (z == 2) ? d2 : d3;
    float4 v = a[i];
    ushort4 hv;
    hv.x = __half_as_ushort(__float2half_rn(v.x));
    hv.y = __half_as_ushort(__float2half_rn(v.y));
    hv.z = __half_as_ushort(__float2half_rn(v.z));
    hv.w = __half_as_ushort(__float2half_rn(v.w));
    *(ushort4*)(d + (size_t)i * 4) = hv;
}

// ---------------------------------------------------------------------------
// fp16 single-pass GEMM: C = A @ B^T. grid.z selects among up to 3 (B, C)
// sets sharing the same A (QKV in one launch). (validated R15)
// ---------------------------------------------------------------------------
#define GBM 128
#define GBN 128
#define GBK 32
#define LDS_W 40
#define TILE_B2 (GBM * LDS_W * 2)   // bytes per buffer = 10240
#define NCHUNK1 (KDIM / GBK)        // 64

__global__ __launch_bounds__(256) void gemm1h_kernel(
    const __half* __restrict__ A,
    const __half* __restrict__ Bh0, float* __restrict__ C0,
    const __half* __restrict__ Bh1, float* __restrict__ C1,
    const __half* __restrict__ Bh2, float* __restrict__ C2)
{
    const int z = blockIdx.z;
    const __half* Bh = (z == 0) ? Bh0 : (z == 1) ? Bh1 : Bh2;
    float* C = (z == 0) ? C0 : (z == 1) ? C1 : C2;

    __shared__ __half sA[2][GBM * LDS_W];
    __shared__ __half sB[2][GBN * LDS_W];

    const int tid = threadIdx.x;
    const int lane = tid & 31;
    const int wid = tid >> 5;
    const int wm = (wid & 3) * 32;
    const int wn = (wid >> 2) * 64;
    const int g = lane >> 2;
    const int t = lane & 3;
    const int lrow = lane & 15;
    const int lsel = (lane >> 4) * 8;

    const int bm = blockIdx.y * GBM;
    const int bn = blockIdx.x * GBN;

    const int grow = tid >> 1;
    const int gcol = (tid & 1) * 16;

    const uint32_t sAu = (uint32_t)__cvta_generic_to_shared(&sA[0][0]);
    const uint32_t sBu = (uint32_t)__cvta_generic_to_shared(&sB[0][0]);

    float acc[2][8][4];
#pragma unroll
    for (int i = 0; i < 2; i++)
#pragma unroll
        for (int j = 0; j < 8; j++)
#pragma unroll
            for (int r = 0; r < 4; r++) acc[i][j][r] = 0.f;

    auto fetch = [&](int c, uint4& ra0, uint4& ra1, uint4& rb0, uint4& rb1) {
        const int k0 = c * GBK;
        const size_t ga = (size_t)(bm + grow) * KDIM + k0 + gcol;
        const size_t gb = (size_t)(bn + grow) * KDIM + k0 + gcol;
        ra0 = *(const uint4*)(A + ga);
        ra1 = *(const uint4*)(A + ga + 8);
        rb0 = *(const uint4*)(Bh + gb);
        rb1 = *(const uint4*)(Bh + gb + 8);
    };
    auto store = [&](int buf, const uint4& ra0, const uint4& ra1,
                     const uint4& rb0, const uint4& rb1) {
        __half* pa = &sA[buf][grow * LDS_W + gcol];
        __half* pb = &sB[buf][grow * LDS_W + gcol];
        *(uint4*)pa = ra0;
        *(uint4*)(pa + 8) = ra1;
        *(uint4*)pb = rb0;
        *(uint4*)(pb + 8) = rb1;
    };

    {
        uint4 ra0, ra1, rb0, rb1;
        fetch(0, ra0, ra1, rb0, rb1);
        store(0, ra0, ra1, rb0, rb1);
    }
    __syncthreads();

    for (int c = 0; c < NCHUNK1; c++) {
        const int buf = c & 1;
        const bool more = (c + 1 < NCHUNK1);
        uint4 ra0, ra1, rb0, rb1;
        if (more) fetch(c + 1, ra0, ra1, rb0, rb1);

        const uint32_t sa = sAu + (uint32_t)buf * TILE_B2;
        const uint32_t sb = sBu + (uint32_t)buf * TILE_B2;
#pragma unroll
        for (int kk = 0; kk < GBK; kk += 16) {
            uint32_t af[2][4];
#pragma unroll
            for (int mt = 0; mt < 2; mt++) {
                const uint32_t ra = sa + (uint32_t)((wm + mt * 16 + lrow) * LDS_W + kk + lsel) * 2;
                LDSM4(af[mt][0], af[mt][1], af[mt][2], af[mt][3], ra);
            }
            uint32_t bfr[8][2];
#pragma unroll
            for (int p = 0; p < 4; p++) {
                const uint32_t rb = sb + (uint32_t)((wn + p * 16 + lrow) * LDS_W + kk + lsel) * 2;
                uint32_t r0, r1, r2, r3;
                LDSM4(r0, r1, r2, r3, rb);
                bfr[2 * p][0] = r0; bfr[2 * p + 1][0] = r1;
                bfr[2 * p][1] = r2; bfr[2 * p + 1][1] = r3;
            }
#pragma unroll
            for (int mt = 0; mt < 2; mt++)
#pragma unroll
                for (int nt = 0; nt < 8; nt++)
                    mma16816h(acc[mt][nt], af[mt], bfr[nt]);
        }

        if (more) store(buf ^ 1, ra0, ra1, rb0, rb1);
        __syncthreads();
    }

#pragma unroll
    for (int mt = 0; mt < 2; mt++) {
        const int r0 = bm + wm + mt * 16 + g;
#pragma unroll
        for (int nt = 0; nt < 8; nt++) {
            const int col = bn + wn + nt * 8 + 2 * t;
            *(float2*)&C[(size_t)r0 * HIDDEN + col] = make_float2(acc[mt][nt][0], acc[mt][nt][1]);
            *(float2*)&C[(size_t)(r0 + 8) * HIDDEN + col] = make_float2(acc[mt][nt][2], acc[mt][nt][3]);
        }
    }
}

// ---------------------------------------------------------------------------
// RoPE + emit fp16: Q split hi/lo (exact to 22 bits), K single-rounded.
// ---------------------------------------------------------------------------
__global__ void rope_split_kernel(const float* __restrict__ q, const float* __restrict__ k,
                                  __half* __restrict__ qh, __half* __restrict__ ql,
                                  __half* __restrict__ kh)
{
    int idx = blockIdx.x * blockDim.x + threadIdx.x;
    int d = idx & 63;
    int m = idx >> 10;
    int l = m & (SEQL - 1);
    int h = (idx >> 6) & (HEADS - 1);

    float e = (2.0f * (float)d) / 128.0f;
    float inv = 1.0f / powf(10000.0f, e);
    float ang = (float)l * inv;
    float s, c;
    sincosf(ang, &s, &c);

    size_t base = (size_t)m * HIDDEN + h * HD + d;
    float q1 = q[base], q2 = q[base + 64];
    float k1 = k[base], k2 = k[base + 64];
    float qa = q1 * c - q2 * s;
    float qb = q2 * c + q1 * s;
    float ka = k1 * c - k2 * s;
    float kb = k2 * c + k1 * s;

    __half t0;
    t0 = __float2half_rn(qa); qh[base] = t0;      ql[base] = __float2half_rn(qa - __half2float(t0));
    t0 = __float2half_rn(qb); qh[base + 64] = t0; ql[base + 64] = __float2half_rn(qb - __half2float(t0));
    kh[base] = __float2half_rn(ka);
    kh[base + 64] = __float2half_rn(kb);
}

// ---------------------------------------------------------------------------
// V transpose + round to single fp16
// ---------------------------------------------------------------------------
__global__ __launch_bounds__(256) void vt_half_kernel(
    const float* __restrict__ v, __half* __restrict__ vt)
{
    __shared__ float tile[32][33];
    const int bh = blockIdx.z;
    const int b = bh >> 4, h = bh & 15;
    const int l0 = blockIdx.x * 32, d0 = blockIdx.y * 32;
    const int tx = threadIdx.x, ty = threadIdx.y;

#pragma unroll
    for (int i = 0; i < 4; i++) {
        int r = ty + i * 8;
        tile[r][tx] = v[(size_t)(b * SEQL + l0 + r) * HIDDEN + h * HD + d0 + tx];
    }
    __syncthreads();
#pragma unroll
    for (int i = 0; i < 4; i++) {
        int r = ty + i * 8;
        size_t o = ((size_t)((b * HEADS + h) * HD + d0 + r)) * SEQL + l0 + tx;
        vt[o] = __float2half_rn(tile[tx][r]);
    }
}

// ---------------------------------------------------------------------------
// Flash attention: S = 2-term fp16 (Qh/Ql x K); PV = 2-term fp16.
// smem: Qh | Ql | K | V  (all fp16) = 105472 B -> 2 CTAs/SM.
// ---------------------------------------------------------------------------
#define QW 136
#define VW 72
#define OQH 0
#define OQL 17408
#define OK  34816
#define OV  43520
#define FLASH_SMEM ((43520 + 128 * VW) * 2) // 105472 bytes

__device__ __forceinline__ void pack_pair(float a, float b, uint32_t& hi_pack, uint32_t& lo_pack)
{
    __half2 h = __floats2half2_rn(a, b);
    hi_pack = *reinterpret_cast<uint32_t*>(&h);
    float ra = a - __half2float(__low2half(h));
    float rb = b - __half2float(__high2half(h));
    __half2 l = __floats2half2_rn(ra, rb);
    lo_pack = *reinterpret_cast<uint32_t*>(&l);
}

__global__ __launch_bounds__(256) void flash_mma_kernel(
    const __half* __restrict__ Qh, const __half* __restrict__ Ql,
    const __half* __restrict__ Kh, const __half* __restrict__ Vt16,
    float* __restrict__ O)
{
    extern __shared__ __half fs[];
    __half* sQh = fs + OQH;
    __half* sQl = fs + OQL;
    __half* sK  = fs + OK;
    __half* sV  = fs + OV;

    const uint32_t fsU = (uint32_t)__cvta_generic_to_shared(fs);
    const uint32_t sQhU = fsU + OQH * 2;
    const uint32_t sQlU = fsU + OQL * 2;
    const uint32_t sKU  = fsU + OK * 2;
    const uint32_t sVU  = fsU + OV * 2;

    const int qt = blockIdx.x, h = blockIdx.y, b = blockIdx.z;
    const int tid = threadIdx.x, lane = tid & 31, wid = tid >> 5;
    const int g = lane >> 2, t = lane & 3;
    const int lrow = lane & 15;
    const int lsel = (lane >> 4) * 8;
    const int wm = wid * 16;
    const float scale = 0.0883883476483184f;

    {
        const size_t base = (size_t)(b * SEQL + qt * 128) * HIDDEN + h * HD;
#pragma unroll
        for (int it = 0; it < 8; it++) {
            int id = tid + it * 256;
            int r = id >> 4, c8 = (id & 15) * 8;
            *(uint4*)&sQh[r * QW + c8] = *(const uint4*)&Qh[base + (size_t)r * HIDDEN + c8];
            *(uint4*)&sQl[r * QW + c8] = *(const uint4*)&Ql[base + (size_t)r * HIDDEN + c8];
        }
    }

    float m0 = -1e30f, m1 = -1e30f, l0 = 0.f, l1 = 0.f;
    float oacc[16][4];
#pragma unroll
    for (int nt = 0; nt < 16; nt++)
#pragma unroll
        for (int r = 0; r < 4; r++) oacc[nt][r] = 0.f;

    const int nkt = 2 * qt + 2;
    for (int kt = 0; kt < nkt; kt++) {
        __syncthreads();
        // K: 64 rows x 16 uint4 = 1024 slots; V: 128 rows x 8 uint4 = 1024 slots.
        // Both need all 4 iterations of 256 threads.
#pragma unroll
        for (int it = 0; it < 4; it++) {
            int id = tid + it * 256;
            int r = id >> 4, c8 = (id & 15) * 8;
            size_t gk = (size_t)(b * SEQL + kt * 64 + r) * HIDDEN + h * HD + c8;
            *(uint4*)&sK[r * QW + c8] = *(const uint4*)&Kh[gk];
            int rv = id >> 3, cv = (id & 7) * 8;
            size_t gv = (size_t)((b * HEADS + h) * HD + rv) * SEQL + kt * 64 + cv;
            *(uint4*)&sV[rv * VW + cv] = *(const uint4*)&Vt16[gv];
        }
        __syncthreads();

        float sacc[8][4];
#pragma unroll
        for (int nt = 0; nt < 8; nt++)
#pragma unroll
            for (int r = 0; r < 4; r++) sacc[nt][r] = 0.f;

#pragma unroll
        for (int kc = 0; kc < 8; kc++) {
            const int kk = kc * 16;
            uint32_t aqh[4], aql[4];
            const uint32_t aoff = (uint32_t)((wm + lrow) * QW + kk + lsel) * 2;
            LDSM4(aqh[0], aqh[1], aqh[2], aqh[3], sQhU + aoff);
            LDSM4(aql[0], aql[1], aql[2], aql[3], sQlU + aoff);
            uint32_t bk[8][2];
#pragma unroll
            for (int p = 0; p < 4; p++) {
                const uint32_t boff = (uint32_t)((p * 16 + lrow) * QW + kk + lsel) * 2;
                uint32_t r0, r1, r2, r3;
                LDSM4(r0, r1, r2, r3, sKU + boff);
                bk[2 * p][0] = r0; bk[2 * p + 1][0] = r1;
                bk[2 * p][1] = r2; bk[2 * p + 1][1] = r3;
            }
#pragma unroll
            for (int nt = 0; nt < 8; nt++) {
                mma16816h(sacc[nt], aqh, bk[nt]);
                mma16816h(sacc[nt], aql, bk[nt]);
            }
        }

        const int row0 = qt * 128 + wm + g;
        const int row1 = row0 + 8;
#pragma unroll
        for (int nt = 0; nt < 8; nt++) {
            sacc[nt][0] *= scale; sacc[nt][1] *= scale;
            sacc[nt][2] *= scale; sacc[nt][3] *= scale;
        }
        if (kt * 64 + 63 > qt * 128 + wm) {
#pragma unroll
            for (int nt = 0; nt < 8; nt++) {
                const int col = kt * 64 + nt * 8 + 2 * t;
                if (col > row0)     sacc[nt][0] = -1e30f;
                if (col + 1 > row0) sacc[nt][1] = -1e30f;
                if (col > row1)     sacc[nt][2] = -1e30f;
                if (col + 1 > row1) sacc[nt][3] = -1e30f;
            }
        }

        float mt0 = -1e30f, mt1 = -1e30f;
#pragma unroll
        for (int nt = 0; nt < 8; nt++) {
            mt0 = fmaxf(mt0, fmaxf(sacc[nt][0], sacc[nt][1]));
            mt1 = fmaxf(mt1, fmaxf(sacc[nt][2], sacc[nt][3]));
        }
        mt0 = fmaxf(mt0, __shfl_xor_sync(0xffffffffu, mt0, 1));
        mt0 = fmaxf(mt0, __shfl_xor_sync(0xffffffffu, mt0, 2));
        mt1 = fmaxf(mt1, __shfl_xor_sync(0xffffffffu, mt1, 1));
        mt1 = fmaxf(mt1, __shfl_xor_sync(0xffffffffu, mt1, 2));

        const float nm0 = fmaxf(m0, mt0), nm1 = fmaxf(m1, mt1);
        const float alpha0 = __expf(m0 - nm0), alpha1 = __expf(m1 - nm1);
        float ps0 = 0.f, ps1 = 0.f;
#pragma unroll
        for (int nt = 0; nt < 8; nt++) {
            sacc[nt][0] = __expf(sacc[nt][0] - nm0);
            sacc[nt][1] = __expf(sacc[nt][1] - nm0);
            sacc[nt][2] = __expf(sacc[nt][2] - nm1);
            sacc[nt][3] = __expf(sacc[nt][3] - nm1);
            ps0 += sacc[nt][0] + sacc[nt][1];
            ps1 += sacc[nt][2] + sacc[nt][3];
        }
        ps0 += __shfl_xor_sync(0xffffffffu, ps0, 1);
        ps0 += __shfl_xor_sync(0xffffffffu, ps0, 2);
        ps1 += __shfl_xor_sync(0xffffffffu, ps1, 1);
        ps1 += __shfl_xor_sync(0xffffffffu, ps1, 2);
        l0 = alpha0 * l0 + ps0; m0 = nm0;
        l1 = alpha1 * l1 + ps1; m1 = nm1;
#pragma unroll
        for (int nt = 0; nt < 16; nt++) {
            oacc[nt][0] *= alpha0; oacc[nt][1] *= alpha0;
            oacc[nt][2] *= alpha1; oacc[nt][3] *= alpha1;
        }

        uint32_t ph[4][4], pl[4][4];
#pragma unroll
        for (int kc = 0; kc < 4; kc++) {
            const int j0 = 2 * kc, j1 = 2 * kc + 1;
            pack_pair(sacc[j0][0], sacc[j0][1], ph[kc][0], pl[kc][0]);
            pack_pair(sacc[j0][2], sacc[j0][3], ph[kc][1], pl[kc][1]);
            pack_pair(sacc[j1][0], sacc[j1][1], ph[kc][2], pl[kc][2]);
            pack_pair(sacc[j1][2], sacc[j1][3], ph[kc][3], pl[kc][3]);
        }

#pragma unroll
        for (int kc = 0; kc < 4; kc++) {
#pragma unroll
            for (int p = 0; p < 8; p++) {
                const uint32_t voff = (uint32_t)((p * 16 + lrow) * VW + kc * 16 + lsel) * 2;
                uint32_t r0, r1, r2, r3;
                LDSM4(r0, r1, r2, r3, sVU + voff);
                uint32_t v0[2] = { r0, r2 };
                uint32_t v1[2] = { r1, r3 };
                mma16816h(oacc[2 * p], ph[kc], v0);
                mma16816h(oacc[2 * p], pl[kc], v0);
                mma16816h(oacc[2 * p + 1], ph[kc], v1);
                mma16816h(oacc[2 * p + 1], pl[kc], v1);
            }
        }
    }

    const float i0 = 1.0f / l0, i1 = 1.0f / l1;
    const size_t rbase = (size_t)(b * SEQL + qt * 128 + wm + g) * HIDDEN + h * HD + 2 * t;
#pragma unroll
    for (int nt = 0; nt < 16; nt++) {
        *(float2*)&O[rbase + nt * 8] = make_float2(oacc[nt][0] * i0, oacc[nt][1] * i0);
        *(float2*)&O[rbase + 8 * HIDDEN + nt * 8] = make_float2(oacc[nt][2] * i1, oacc[nt][3] * i1);
    }
}

// ---------------------------------------------------------------------------
extern "C" void kernel_launch(void* const* d_in, const int* in_sizes, int n_in,
                              void* d_out, int out_size)
{
    const float* x  = (const float*)d_in[0];
    const float* wq = (const float*)d_in[1];
    const float* wk = (const float*)d_in[2];
    const float* wv = (const float*)d_in[3];
    const float* wo = (const float*)d_in[4];
    float* out = (float*)d_out;

    float *q, *k, *v, *o;
    cudaGetSymbolAddress((void**)&q, g_q);
    cudaGetSymbolAddress((void**)&k, g_k);
    cudaGetSymbolAddress((void**)&v, g_v);
    cudaGetSymbolAddress((void**)&o, g_o);

    __half *x16, *o16, *wq16, *wk16, *wv16, *wo16;
    __half *qh16, *ql16, *kh16, *vt16;
    cudaGetSymbolAddress((void**)&x16, g_x16);
    cudaGetSymbolAddress((void**)&o16, g_o16);
    cudaGetSymbolAddress((void**)&wq16, g_wq16);
    cudaGetSymbolAddress((void**)&wk16, g_wk16);
    cudaGetSymbolAddress((void**)&wv16, g_wv16);
    cudaGetSymbolAddress((void**)&wo16, g_wo16);
    cudaGetSymbolAddress((void**)&qh16, g_qh16);
    cudaGetSymbolAddress((void**)&ql16, g_ql16);
    cudaGetSymbolAddress((void**)&kh16, g_kh16);
    cudaGetSymbolAddress((void**)&vt16, g_vt16);

    const int nx4 = MROWS * HIDDEN / 4;
    const int nw4 = HIDDEN * HIDDEN / 4;
    round_h_kernel<<<(nx4 + 255) / 256, 256>>>((const float4*)x, x16, nx4);
    round_h4_kernel<<<dim3((nw4 + 255) / 256, 1, 4), 256>>>(
        (const float4*)wq, wq16, (const float4*)wk, wk16,
        (const float4*)wv, wv16, (const float4*)wo, wo16, nw4);

    dim3 gg(HIDDEN / GBN, MROWS / GBM); // (16, 32)
    gemm1h_kernel<<<dim3(gg.x, gg.y, 3), 256>>>(
        x16, wq16, q, wk16, k, wv16, v);

    rope_split_kernel<<<(MROWS * HEADS * 64) / 256, 256>>>(q, k, qh16, ql16, kh16);
    vt_half_kernel<<<dim3(SEQL / 32, HD / 32, NBATCH * HEADS), dim3(32, 8)>>>(v, vt16);

    cudaFuncSetAttribute(flash_mma_kernel, cudaFuncAttributeMaxDynamicSharedMemorySize, FLASH_SMEM);
    flash_mma_kernel<<<dim3(SEQL / 128, HEADS, NBATCH), 256, FLASH_SMEM>>>(
        qh16, ql16, kh16, vt16, o);

    round_h_kernel<<<(nx4 + 255) / 256, 256>>>((const float4*)o, o16, nx4);
    gemm1h_kernel<<<dim3(gg.x, gg.y, 1), 256>>>(
        o16, wo16, out, wo16, out, wo16, out);
}